// round 13
// baseline (speedup 1.0000x reference)
#include <cuda_runtime.h>
#include <cuda_bf16.h>
#include <cuda_fp16.h>
#include <cstdint>

#define Nn 8192
#define Dd 512
#define EPSf 1e-8f
#define LOG2E 1.4426950408889634f

#define BM 128
#define BN 128
#define NRB (Nn / BM)       // 64
#define NCT (Nn / BN)       // 64
#define NITEMS (NRB * NCT)  // 4096
#define NCTA_G 296          // exactly 1 resident wave (2 CTAs/SM x 148 SMs)
#define NWARPS_G (NCTA_G * 8)   // 2368 warps for the norm phase

#define A_BYTES (BM * Dd)        // 65536 — A tile resident
#define B_STG (BN * 128)         // 16384 per stage (128B of K)
#define DYN_SMEM (A_BYTES + 2 * B_STG)   // 98304 — proven 2 CTAs/SM

#define RED_BLOCKS 128
#define RED_ROWS (Nn / RED_BLOCKS)   // 64 rows per block

// ---- scratch ----
__device__ unsigned char g_A8[(size_t)Nn * Dd];
__device__ unsigned char g_P8[(size_t)Nn * Dd];
__device__ float g_pos[Nn];
__device__ float g_diag[Nn];
__device__ float g_norm2[Nn];
__device__ float g_partial[NCT][Nn];
__device__ float g_s1loss[RED_BLOCKS];
__device__ float g_s1sq[RED_BLOCKS];
__device__ int   g_red_ctr = 0;
__device__ int   g_bar1 = 0;
__device__ int   g_bar2 = 0;

__device__ __forceinline__ void cpa16(uint32_t dst, const void* src) {
    asm volatile("cp.async.cg.shared.global [%0], [%1], 16;\n" :: "r"(dst), "l"(src));
}
__device__ __forceinline__ void cp_commit() {
    asm volatile("cp.async.commit_group;\n" ::);
}
#define CP_WAIT(n) asm volatile("cp.async.wait_group %0;\n" :: "n"(n))

__device__ __forceinline__ void ldm4(uint32_t* r, uint32_t addr) {
    asm volatile("ldmatrix.sync.aligned.m8n8.x4.shared.b16 {%0,%1,%2,%3}, [%4];\n"
                 : "=r"(r[0]), "=r"(r[1]), "=r"(r[2]), "=r"(r[3]) : "r"(addr));
}
__device__ __forceinline__ void mma_fp8_h(uint32_t* c, const uint32_t* a,
                                          uint32_t b0, uint32_t b1) {
    asm volatile(
        "mma.sync.aligned.m16n8k32.row.col.f16.e4m3.e4m3.f16 "
        "{%0,%1}, {%2,%3,%4,%5}, {%6,%7}, {%0,%1};\n"
        : "+r"(c[0]), "+r"(c[1])
        : "r"(a[0]), "r"(a[1]), "r"(a[2]), "r"(a[3]), "r"(b0), "r"(b1));
}
__device__ __forceinline__ float ex2f(float x) {
    float r;
    asm("ex2.approx.f32 %0, %1;" : "=f"(r) : "f"(x));
    return r;
}

// ---- helpers for the GEMM phase ----
__device__ __forceinline__ void load_A_tile(uint32_t smA, const unsigned char* Ag,
                                            int tid) {
#pragma unroll
    for (int u = 0; u < 16; u++) {
        int e = tid + u * 256;               // 4096 16B-chunks
        int r = e >> 5, ch = e & 31;
        cpa16(smA + r * 512 + (((uint32_t)(ch ^ (r & 7))) << 4),
              Ag + (size_t)r * Dd + ch * 16);
    }
}
__device__ __forceinline__ void load_B_slab(uint32_t dst0, const unsigned char* Bg,
                                            int kt, int tid) {
#pragma unroll
    for (int u = 0; u < 4; u++) {
        int e = tid + u * 256;               // 1024 chunks
        int r = e >> 3, ch = e & 7;
        cpa16(dst0 + r * 128 + (((uint32_t)(ch ^ (r & 7))) << 4),
              Bg + (size_t)r * Dd + kt * 128 + ch * 16);
    }
}

// norm one row (R11-proven single-pass)
__device__ __forceinline__ void norm_row(const float* __restrict__ ex, int gw,
                                         int lane) {
    const float4* a4 = reinterpret_cast<const float4*>(ex + (size_t)gw * 2 * Dd);
    const float4* p4 = a4 + Dd / 4;

    float4 av[4], pv[4];
    float an2 = 0.f, pn2 = 0.f, dt = 0.f;
#pragma unroll
    for (int i = 0; i < 4; i++) {
        av[i] = a4[lane + 32 * i];
        pv[i] = p4[lane + 32 * i];
        an2 += av[i].x * av[i].x + av[i].y * av[i].y + av[i].z * av[i].z + av[i].w * av[i].w;
        pn2 += pv[i].x * pv[i].x + pv[i].y * pv[i].y + pv[i].z * pv[i].z + pv[i].w * pv[i].w;
        dt  += av[i].x * pv[i].x + av[i].y * pv[i].y + av[i].z * pv[i].z + av[i].w * pv[i].w;
    }
#pragma unroll
    for (int o = 16; o; o >>= 1) {
        an2 += __shfl_xor_sync(0xffffffffu, an2, o);
        pn2 += __shfl_xor_sync(0xffffffffu, pn2, o);
        dt  += __shfl_xor_sync(0xffffffffu, dt, o);
    }
    float an = sqrtf(an2), pn = sqrtf(pn2);
    float ia = LOG2E / an;    // fold log2(e) into A
    float ip = 1.0f / pn;

#pragma unroll
    for (int i = 0; i < 4; i++) {
        int byteoff = (lane + 32 * i) * 4;
        uint16_t u01, u23;
        asm("cvt.rn.satfinite.e4m3x2.f32 %0, %1, %2;"
            : "=h"(u01) : "f"(av[i].y * ia), "f"(av[i].x * ia));
        asm("cvt.rn.satfinite.e4m3x2.f32 %0, %1, %2;"
            : "=h"(u23) : "f"(av[i].w * ia), "f"(av[i].z * ia));
        uint32_t w = (uint32_t)u01 | ((uint32_t)u23 << 16);
        *reinterpret_cast<uint32_t*>(&g_A8[(size_t)gw * Dd + byteoff]) = w;

        asm("cvt.rn.satfinite.e4m3x2.f32 %0, %1, %2;"
            : "=h"(u01) : "f"(pv[i].y * ip), "f"(pv[i].x * ip));
        asm("cvt.rn.satfinite.e4m3x2.f32 %0, %1, %2;"
            : "=h"(u23) : "f"(pv[i].w * ip), "f"(pv[i].z * ip));
        w = (uint32_t)u01 | ((uint32_t)u23 << 16);
        *reinterpret_cast<uint32_t*>(&g_P8[(size_t)gw * Dd + byteoff]) = w;
    }
    if (lane == 0) {
        g_pos[gw]   = dt / fmaxf(an * pn, EPSf);            // raw cos
        g_diag[gw]  = LOG2E * (an2 / fmaxf(an2, EPSf));     // log2 domain
        g_norm2[gw] = an2 + pn2;
    }
}

// ============================================================
// Fused kernel: phase 1 norm -> grid barrier -> phase 2 GEMM.
// 296 CTAs = exactly one resident wave (2 CTAs/SM), so the
// software grid barrier cannot deadlock.
// ============================================================
__global__ void __launch_bounds__(256, 2) k_fused(const float* __restrict__ ex) {
    extern __shared__ __align__(128) unsigned char sm[];
    __shared__ float srow[2][BM];

    const uint32_t smb = (uint32_t)__cvta_generic_to_shared(sm);
    const uint32_t smA = smb;

    const int tid = threadIdx.x;
    const int lane = tid & 31;
    const int warp = tid >> 5;
    const int wm = warp >> 1;     // 0..3
    const int wn = warp & 1;      // 0..1

    // ================= phase 1: normalize rows =================
    {
        int gwarp = blockIdx.x * 8 + warp;       // 0..2367
#pragma unroll 1
        for (int row = gwarp; row < Nn; row += NWARPS_G)
            norm_row(ex, row, lane);
    }

    // ================= grid barrier (deterministic, replay-safe) ====
    __syncthreads();
    if (tid == 0) {
        __threadfence();
        atomicAdd(&g_bar1, 1);
        while (atomicAdd(&g_bar1, 0) < NCTA_G) __nanosleep(64);
        __threadfence();
    }
    __syncthreads();
    if (tid == 0) {
        int t = atomicAdd(&g_bar2, 1);
        if (t == NCTA_G - 1) {       // last CTA past the wait resets both
            g_bar1 = 0;
            g_bar2 = 0;
            __threadfence();
        }
    }

    // ================= phase 2: GEMM (R11-frozen pipeline) ==========
    const int lo = (int)(((long long)blockIdx.x * NITEMS) / NCTA_G);
    const int hi = (int)(((long long)(blockIdx.x + 1) * NITEMS) / NCTA_G);

    int rb = lo >> 6;

    // prologue: A tile + first B slab
    load_A_tile(smA, g_A8 + (size_t)(rb * BM) * Dd, tid);
    load_B_slab(smb + A_BYTES, g_P8 + (size_t)((lo & 63) * BN) * Dd, 0, tid);
    cp_commit();

    uint32_t c[2][8][2];
#pragma unroll
    for (int mi = 0; mi < 2; mi++)
#pragma unroll
        for (int nj = 0; nj < 8; nj++) {
            c[mi][nj][0] = 0u; c[mi][nj][1] = 0u;
        }

    // hoisted invariant swizzled offsets
    uint32_t a_off[2], b_off[4];
#pragma unroll
    for (int mi = 0; mi < 2; mi++) {
        int r = wm * 32 + mi * 16 + (lane & 7) + ((lane >> 3) & 1) * 8;
        a_off[mi] = smA + r * 512 + ((uint32_t)(r & 7) << 4);
    }
#pragma unroll
    for (int ng = 0; ng < 4; ng++) {
        int r = wn * 64 + ng * 16 + (lane & 7) + ((lane >> 4) << 3);
        b_off[ng] = r * 128 + ((uint32_t)(r & 7) << 4);
    }
    const int a_chb = (lane >> 4);            // 0/1
    const int b_chb = ((lane >> 3) & 1);      // 0/1

    int buf = 0;

#pragma unroll 1
    for (int it = lo; it < hi; ++it) {
        const int ct = it & 63;
        const unsigned char* Bg = g_P8 + (size_t)(ct * BN) * Dd;

#pragma unroll
        for (int kt = 0; kt < 4; kt++) {
            CP_WAIT(0);          // current slab (+A at entry/boundary) complete
            __syncthreads();     // all warps done with buffer being refilled

            if (kt < 3) {
                load_B_slab(smb + A_BYTES + (buf ^ 1) * B_STG, Bg, kt + 1, tid);
                cp_commit();
            } else if (it + 1 < hi) {
                load_B_slab(smb + A_BYTES + (buf ^ 1) * B_STG,
                            g_P8 + (size_t)(((it + 1) & 63) * BN) * Dd, 0, tid);
                cp_commit();
            } else {
                cp_commit();
            }

            // ---- compute current buffer against resident A ----
            const uint32_t bst = smb + A_BYTES + buf * B_STG;
#pragma unroll
            for (int ks = 0; ks < 4; ks++) {
                uint32_t a[2][4];
                const uint32_t a_chx = (uint32_t)(kt * 8 + ks * 2 + a_chb) << 4;
#pragma unroll
                for (int mi = 0; mi < 2; mi++)
                    ldm4(a[mi], a_off[mi] ^ a_chx);
                const uint32_t b_chx = (uint32_t)(ks * 2 + b_chb) << 4;
#pragma unroll
                for (int ng = 0; ng < 4; ng++) {
                    uint32_t b[4];
                    ldm4(b, bst + (b_off[ng] ^ b_chx));
#pragma unroll
                    for (int mi = 0; mi < 2; mi++) {
                        mma_fp8_h(c[mi][2 * ng + 0], a[mi], b[0], b[1]);
                        mma_fp8_h(c[mi][2 * ng + 1], a[mi], b[2], b[3]);
                    }
                }
            }
            buf ^= 1;
        }

        // ---- item finished: fused ex2-row-sum epilogue + flush ----
        {
            const int row0 = rb * BM;
            const int jcol = ct * BN;
            const bool hd = (row0 == jcol);
            float rowacc[4];
#pragma unroll
            for (int mi = 0; mi < 2; mi++) {
                float s0 = 0.f, s1 = 0.f;
                int gi0 = row0 + wm * 32 + mi * 16 + (lane >> 2);
                int gi8 = gi0 + 8;
#pragma unroll
                for (int nj = 0; nj < 8; nj++) {
                    int gj = jcol + wn * 64 + nj * 8 + ((lane & 3) << 1);
                    float2 f01 = __half22float2(
                        *reinterpret_cast<__half2*>(&c[mi][nj][0]));
                    float2 f23 = __half22float2(
                        *reinterpret_cast<__half2*>(&c[mi][nj][1]));
                    float v0 = f01.x, v1 = f01.y;
                    float v2 = f23.x, v3 = f23.y;
                    if (hd) {
                        if (gi0 == gj)     v0 = g_diag[gi0];
                        if (gi0 == gj + 1) v1 = g_diag[gi0];
                        if (gi8 == gj)     v2 = g_diag[gi8];
                        if (gi8 == gj + 1) v3 = g_diag[gi8];
                    }
                    s0 += ex2f(v0) + ex2f(v1);
                    s1 += ex2f(v2) + ex2f(v3);
                    c[mi][nj][0] = 0u; c[mi][nj][1] = 0u;
                }
                rowacc[mi * 2 + 0] = s0;
                rowacc[mi * 2 + 1] = s1;
            }
#pragma unroll
            for (int k = 0; k < 4; k++) {
                rowacc[k] += __shfl_xor_sync(0xffffffffu, rowacc[k], 1);
                rowacc[k] += __shfl_xor_sync(0xffffffffu, rowacc[k], 2);
            }
            if ((lane & 3) == 0) {
                int lr = wm * 32 + (lane >> 2);
                srow[wn][lr +  0] = rowacc[0];
                srow[wn][lr +  8] = rowacc[1];
                srow[wn][lr + 16] = rowacc[2];
                srow[wn][lr + 24] = rowacc[3];
            }
            __syncthreads();   // srow ready; also: all warps done reading A
            if (tid < BM)
                g_partial[ct][row0 + tid] = srow[0][tid] + srow[1][tid];
        }

        // rb boundary: reload A for next item (safe: post-sync)
        if (it + 1 < hi) {
            const int rb2 = (it + 1) >> 6;
            if (rb2 != rb) {
                rb = rb2;
                load_A_tile(smA, g_A8 + (size_t)(rb2 * BM) * Dd, tid);
                cp_commit();
            }
        }
    }
}

// ============================================================
// Kernel 3: per-row reduction over 64 partials (128 CTAs x 64 rows),
// fused deterministic final reduce in the last-arriving block.
// ============================================================
__global__ void __launch_bounds__(64) k_red(float* __restrict__ out) {
    __shared__ float sL[64];
    __shared__ float sS[64];
    __shared__ bool amLast;
    const int tid = threadIdx.x;
    const int i = blockIdx.x * RED_ROWS + tid;   // 64 rows per block

    float rs = 0.f;
#pragma unroll
    for (int cidx = 0; cidx < NCT; cidx++) rs += g_partial[cidx][i];
    float pos = g_pos[i];
    sL[tid] = logf(rs + __expf(pos)) - pos;
    sS[tid] = g_norm2[i];
    __syncthreads();
#pragma unroll
    for (int o = 32; o; o >>= 1) {
        if (tid < o) { sL[tid] += sL[tid + o]; sS[tid] += sS[tid + o]; }
        __syncthreads();
    }
    if (tid == 0) {
        g_s1loss[blockIdx.x] = sL[0];
        g_s1sq[blockIdx.x]   = sS[0];
        __threadfence();
        int t = atomicAdd(&g_red_ctr, 1);
        amLast = (t == RED_BLOCKS - 1);
    }
    __syncthreads();

    if (amLast) {
        sL[tid] = g_s1loss[tid] + g_s1loss[tid + 64];
        sS[tid] = g_s1sq[tid]   + g_s1sq[tid + 64];
        __syncthreads();
#pragma unroll
        for (int o = 32; o; o >>= 1) {
            if (tid < o) { sL[tid] += sL[tid + o]; sS[tid] += sS[tid + o]; }
            __syncthreads();
        }
        if (tid == 0) {
            out[0] = sL[0] / (float)Nn + 0.02f * sqrtf(sS[0]);
            g_red_ctr = 0;    // reset for next graph replay
        }
    }
}

// ============================================================
extern "C" void kernel_launch(void* const* d_in, const int* in_sizes, int n_in,
                              void* d_out, int out_size) {
    const float* ex = (const float*)d_in[0];
    (void)in_sizes; (void)n_in; (void)out_size;

    cudaFuncSetAttribute(k_fused, cudaFuncAttributeMaxDynamicSharedMemorySize, DYN_SMEM);

    k_fused<<<NCTA_G, 256, DYN_SMEM>>>(ex);

    k_red<<<RED_BLOCKS, 64>>>((float*)d_out);
}

// round 14
// speedup vs baseline: 1.0134x; 1.0134x over previous
#include <cuda_runtime.h>
#include <cuda_bf16.h>
#include <cuda_fp16.h>
#include <cstdint>

#define Nn 8192
#define Dd 512
#define EPSf 1e-8f
#define LOG2E 1.4426950408889634f

#define BM 128
#define BN 128
#define NRB (Nn / BM)       // 64
#define NCT (Nn / BN)       // 64
#define NITEMS (NRB * NCT)  // 4096
#define NCTA_G 592          // exactly 2 waves at 2 CTAs/SM on 148 SMs

#define A_BYTES (BM * Dd)        // 65536 — A tile resident
#define B_STG (BN * 128)         // 16384 per stage (128B of K)
#define DYN_SMEM (A_BYTES + 2 * B_STG)   // 98304 — proven 2 CTAs/SM

#define RED_BLOCKS 128
#define RED_ROWS (Nn / RED_BLOCKS)   // 64 rows per block

// ---- scratch ----
__device__ unsigned char g_A8[(size_t)Nn * Dd];
__device__ unsigned char g_P8[(size_t)Nn * Dd];
__device__ float g_pos[Nn];
__device__ float g_diag[Nn];
__device__ float g_norm2[Nn];
__device__ float g_partial[NCT][Nn];
__device__ float g_s1loss[RED_BLOCKS];
__device__ float g_s1sq[RED_BLOCKS];
__device__ int   g_red_ctr = 0;

__device__ __forceinline__ void cpa16(uint32_t dst, const void* src) {
    asm volatile("cp.async.cg.shared.global [%0], [%1], 16;\n" :: "r"(dst), "l"(src));
}
__device__ __forceinline__ void cp_commit() {
    asm volatile("cp.async.commit_group;\n" ::);
}
#define CP_WAIT(n) asm volatile("cp.async.wait_group %0;\n" :: "n"(n))

__device__ __forceinline__ void ldm4(uint32_t* r, uint32_t addr) {
    asm volatile("ldmatrix.sync.aligned.m8n8.x4.shared.b16 {%0,%1,%2,%3}, [%4];\n"
                 : "=r"(r[0]), "=r"(r[1]), "=r"(r[2]), "=r"(r[3]) : "r"(addr));
}
__device__ __forceinline__ void mma_fp8_h(uint32_t* c, const uint32_t* a,
                                          uint32_t b0, uint32_t b1) {
    asm volatile(
        "mma.sync.aligned.m16n8k32.row.col.f16.e4m3.e4m3.f16 "
        "{%0,%1}, {%2,%3,%4,%5}, {%6,%7}, {%0,%1};\n"
        : "+r"(c[0]), "+r"(c[1])
        : "r"(a[0]), "r"(a[1]), "r"(a[2]), "r"(a[3]), "r"(b0), "r"(b1));
}
__device__ __forceinline__ float ex2f(float x) {
    float r;
    asm("ex2.approx.f32 %0, %1;" : "=f"(r) : "f"(x));
    return r;
}

// ============================================================
// Kernel 1 (R11-proven): per-row norms, normalized fp8 copies.
// ============================================================
__global__ void __launch_bounds__(256) k_norm(const float* __restrict__ ex) {
    int gw = (blockIdx.x * 256 + threadIdx.x) >> 5;
    int lane = threadIdx.x & 31;
    if (gw >= Nn) return;

    const float4* a4 = reinterpret_cast<const float4*>(ex + (size_t)gw * 2 * Dd);
    const float4* p4 = a4 + Dd / 4;

    float4 av[4], pv[4];
    float an2 = 0.f, pn2 = 0.f, dt = 0.f;
#pragma unroll
    for (int i = 0; i < 4; i++) {
        av[i] = a4[lane + 32 * i];
        pv[i] = p4[lane + 32 * i];
        an2 += av[i].x * av[i].x + av[i].y * av[i].y + av[i].z * av[i].z + av[i].w * av[i].w;
        pn2 += pv[i].x * pv[i].x + pv[i].y * pv[i].y + pv[i].z * pv[i].z + pv[i].w * pv[i].w;
        dt  += av[i].x * pv[i].x + av[i].y * pv[i].y + av[i].z * pv[i].z + av[i].w * pv[i].w;
    }
#pragma unroll
    for (int o = 16; o; o >>= 1) {
        an2 += __shfl_xor_sync(0xffffffffu, an2, o);
        pn2 += __shfl_xor_sync(0xffffffffu, pn2, o);
        dt  += __shfl_xor_sync(0xffffffffu, dt, o);
    }
    float an = sqrtf(an2), pn = sqrtf(pn2);
    float ia = LOG2E / an;
    float ip = 1.0f / pn;

#pragma unroll
    for (int i = 0; i < 4; i++) {
        int byteoff = (lane + 32 * i) * 4;
        uint16_t u01, u23;
        asm("cvt.rn.satfinite.e4m3x2.f32 %0, %1, %2;"
            : "=h"(u01) : "f"(av[i].y * ia), "f"(av[i].x * ia));
        asm("cvt.rn.satfinite.e4m3x2.f32 %0, %1, %2;"
            : "=h"(u23) : "f"(av[i].w * ia), "f"(av[i].z * ia));
        uint32_t w = (uint32_t)u01 | ((uint32_t)u23 << 16);
        *reinterpret_cast<uint32_t*>(&g_A8[(size_t)gw * Dd + byteoff]) = w;

        asm("cvt.rn.satfinite.e4m3x2.f32 %0, %1, %2;"
            : "=h"(u01) : "f"(pv[i].y * ip), "f"(pv[i].x * ip));
        asm("cvt.rn.satfinite.e4m3x2.f32 %0, %1, %2;"
            : "=h"(u23) : "f"(pv[i].w * ip), "f"(pv[i].z * ip));
        w = (uint32_t)u01 | ((uint32_t)u23 << 16);
        *reinterpret_cast<uint32_t*>(&g_P8[(size_t)gw * Dd + byteoff]) = w;
    }
    if (lane == 0) {
        g_pos[gw]   = dt / fmaxf(an * pn, EPSf);            // raw cos
        g_diag[gw]  = LOG2E * (an2 / fmaxf(an2, EPSf));     // log2 domain
        g_norm2[gw] = an2 + pn2;
    }
}

// ---- helpers for the GEMM kernel ----
__device__ __forceinline__ void load_A_tile(uint32_t smA, const unsigned char* Ag,
                                            int tid) {
#pragma unroll
    for (int u = 0; u < 16; u++) {
        int e = tid + u * 256;               // 4096 16B-chunks
        int r = e >> 5, ch = e & 31;
        cpa16(smA + r * 512 + (((uint32_t)(ch ^ (r & 7))) << 4),
              Ag + (size_t)r * Dd + ch * 16);
    }
}
__device__ __forceinline__ void load_B_slab(uint32_t dst0, const unsigned char* Bg,
                                            int kt, int tid) {
#pragma unroll
    for (int u = 0; u < 4; u++) {
        int e = tid + u * 256;               // 1024 chunks
        int r = e >> 3, ch = e & 7;
        cpa16(dst0 + r * 128 + (((uint32_t)(ch ^ (r & 7))) << 4),
              Bg + (size_t)r * Dd + kt * 128 + ch * 16);
    }
}

// ============================================================
// Kernel 2 (FROZEN — at sm_103 QMMA pipe floor): coarse-persistent
// fp8 GEMM. 592 CTAs (exactly 2 waves), contiguous rb-major ranges,
// compile-time kt loop, A resident per rb, B double-buffered.
// ============================================================
__global__ void __launch_bounds__(256, 2) k_gemm() {
    extern __shared__ __align__(128) unsigned char sm[];
    __shared__ float srow[2][BM];

    const uint32_t smb = (uint32_t)__cvta_generic_to_shared(sm);
    const uint32_t smA = smb;

    const int tid = threadIdx.x;
    const int lane = tid & 31;
    const int warp = tid >> 5;
    const int wm = warp >> 1;     // 0..3
    const int wn = warp & 1;      // 0..1

    const int lo = (int)(((long long)blockIdx.x * NITEMS) / NCTA_G);
    const int hi = (int)(((long long)(blockIdx.x + 1) * NITEMS) / NCTA_G);

    int rb = lo >> 6;

    // ---- prologue: A tile + first B slab (one group) ----
    load_A_tile(smA, g_A8 + (size_t)(rb * BM) * Dd, tid);
    load_B_slab(smb + A_BYTES, g_P8 + (size_t)((lo & 63) * BN) * Dd, 0, tid);
    cp_commit();

    uint32_t c[2][8][2];
#pragma unroll
    for (int mi = 0; mi < 2; mi++)
#pragma unroll
        for (int nj = 0; nj < 8; nj++) {
            c[mi][nj][0] = 0u; c[mi][nj][1] = 0u;
        }

    // hoisted invariant swizzled offsets
    uint32_t a_off[2], b_off[4];
#pragma unroll
    for (int mi = 0; mi < 2; mi++) {
        int r = wm * 32 + mi * 16 + (lane & 7) + ((lane >> 3) & 1) * 8;
        a_off[mi] = smA + r * 512 + ((uint32_t)(r & 7) << 4);
    }
#pragma unroll
    for (int ng = 0; ng < 4; ng++) {
        int r = wn * 64 + ng * 16 + (lane & 7) + ((lane >> 4) << 3);
        b_off[ng] = r * 128 + ((uint32_t)(r & 7) << 4);
    }
    const int a_chb = (lane >> 4);            // 0/1
    const int b_chb = ((lane >> 3) & 1);      // 0/1

    int buf = 0;

#pragma unroll 1
    for (int it = lo; it < hi; ++it) {
        const int ct = it & 63;
        const unsigned char* Bg = g_P8 + (size_t)(ct * BN) * Dd;

#pragma unroll
        for (int kt = 0; kt < 4; kt++) {
            CP_WAIT(0);          // current slab (+A at entry/boundary) complete
            __syncthreads();     // all warps done with buffer being refilled

            if (kt < 3) {
                load_B_slab(smb + A_BYTES + (buf ^ 1) * B_STG, Bg, kt + 1, tid);
                cp_commit();
            } else if (it + 1 < hi) {
                load_B_slab(smb + A_BYTES + (buf ^ 1) * B_STG,
                            g_P8 + (size_t)(((it + 1) & 63) * BN) * Dd, 0, tid);
                cp_commit();
            } else {
                cp_commit();
            }

            // ---- compute current buffer against resident A ----
            const uint32_t bst = smb + A_BYTES + buf * B_STG;
#pragma unroll
            for (int ks = 0; ks < 4; ks++) {
                uint32_t a[2][4];
                const uint32_t a_chx = (uint32_t)(kt * 8 + ks * 2 + a_chb) << 4;
#pragma unroll
                for (int mi = 0; mi < 2; mi++)
                    ldm4(a[mi], a_off[mi] ^ a_chx);
                const uint32_t b_chx = (uint32_t)(ks * 2 + b_chb) << 4;
#pragma unroll
                for (int ng = 0; ng < 4; ng++) {
                    uint32_t b[4];
                    ldm4(b, bst + (b_off[ng] ^ b_chx));
#pragma unroll
                    for (int mi = 0; mi < 2; mi++) {
                        mma_fp8_h(c[mi][2 * ng + 0], a[mi], b[0], b[1]);
                        mma_fp8_h(c[mi][2 * ng + 1], a[mi], b[2], b[3]);
                    }
                }
            }
            buf ^= 1;
        }

        // ---- item finished: fused ex2-row-sum epilogue + flush ----
        {
            const int row0 = rb * BM;
            const int jcol = ct * BN;
            const bool hd = (row0 == jcol);
            float rowacc[4];
#pragma unroll
            for (int mi = 0; mi < 2; mi++) {
                float s0 = 0.f, s1 = 0.f;
                int gi0 = row0 + wm * 32 + mi * 16 + (lane >> 2);
                int gi8 = gi0 + 8;
#pragma unroll
                for (int nj = 0; nj < 8; nj++) {
                    int gj = jcol + wn * 64 + nj * 8 + ((lane & 3) << 1);
                    float2 f01 = __half22float2(
                        *reinterpret_cast<__half2*>(&c[mi][nj][0]));
                    float2 f23 = __half22float2(
                        *reinterpret_cast<__half2*>(&c[mi][nj][1]));
                    float v0 = f01.x, v1 = f01.y;
                    float v2 = f23.x, v3 = f23.y;
                    if (hd) {
                        if (gi0 == gj)     v0 = g_diag[gi0];
                        if (gi0 == gj + 1) v1 = g_diag[gi0];
                        if (gi8 == gj)     v2 = g_diag[gi8];
                        if (gi8 == gj + 1) v3 = g_diag[gi8];
                    }
                    s0 += ex2f(v0) + ex2f(v1);
                    s1 += ex2f(v2) + ex2f(v3);
                    c[mi][nj][0] = 0u; c[mi][nj][1] = 0u;
                }
                rowacc[mi * 2 + 0] = s0;
                rowacc[mi * 2 + 1] = s1;
            }
#pragma unroll
            for (int k = 0; k < 4; k++) {
                rowacc[k] += __shfl_xor_sync(0xffffffffu, rowacc[k], 1);
                rowacc[k] += __shfl_xor_sync(0xffffffffu, rowacc[k], 2);
            }
            if ((lane & 3) == 0) {
                int lr = wm * 32 + (lane >> 2);
                srow[wn][lr +  0] = rowacc[0];
                srow[wn][lr +  8] = rowacc[1];
                srow[wn][lr + 16] = rowacc[2];
                srow[wn][lr + 24] = rowacc[3];
            }
            __syncthreads();   // srow ready; also: all warps done reading A
            if (tid < BM)
                g_partial[ct][row0 + tid] = srow[0][tid] + srow[1][tid];
        }

        // rb boundary: reload A for next item (safe: post-sync)
        if (it + 1 < hi) {
            const int rb2 = (it + 1) >> 6;
            if (rb2 != rb) {
                rb = rb2;
                load_A_tile(smA, g_A8 + (size_t)(rb2 * BM) * Dd, tid);
                cp_commit();
            }
        }
    }
}

// ============================================================
// Kernel 3: per-row reduction over 64 partials. 128 CTAs x 256
// threads; 4 chunk-groups of 64 threads each sum 16 partials
// (coalesced), combined fixed-order in smem, then 64->1 block
// reduce and fused last-block final reduce.
// ============================================================
__global__ void __launch_bounds__(256) k_red(float* __restrict__ out) {
    __shared__ float sP[4][64];
    __shared__ float sL[64];
    __shared__ float sS[64];
    __shared__ bool amLast;
    const int tid = threadIdx.x;
    const int chunk = tid >> 6;          // 0..3
    const int rloc = tid & 63;           // row within block
    const int i = blockIdx.x * RED_ROWS + rloc;

    float rs = 0.f;
#pragma unroll
    for (int c = 0; c < 16; c++) rs += g_partial[chunk * 16 + c][i];
    sP[chunk][rloc] = rs;
    __syncthreads();

    if (tid < 64) {
        float tot = sP[0][tid] + sP[1][tid] + sP[2][tid] + sP[3][tid];
        float pos = g_pos[i];
        sL[tid] = logf(tot + __expf(pos)) - pos;
        sS[tid] = g_norm2[i];
    }
    __syncthreads();
#pragma unroll
    for (int o = 32; o; o >>= 1) {
        if (tid < o) { sL[tid] += sL[tid + o]; sS[tid] += sS[tid + o]; }
        __syncthreads();
    }
    if (tid == 0) {
        g_s1loss[blockIdx.x] = sL[0];
        g_s1sq[blockIdx.x]   = sS[0];
        __threadfence();
        int t = atomicAdd(&g_red_ctr, 1);
        amLast = (t == RED_BLOCKS - 1);
    }
    __syncthreads();

    if (amLast && tid < 64) {
        sL[tid] = g_s1loss[tid] + g_s1loss[tid + 64];
        sS[tid] = g_s1sq[tid]   + g_s1sq[tid + 64];
        __syncthreads();
#pragma unroll
        for (int o = 32; o; o >>= 1) {
            if (tid < o) { sL[tid] += sL[tid + o]; sS[tid] += sS[tid + o]; }
            __syncthreads();
        }
        if (tid == 0) {
            out[0] = sL[0] / (float)Nn + 0.02f * sqrtf(sS[0]);
            g_red_ctr = 0;    // reset for next graph replay
        }
    }
}

// ============================================================
extern "C" void kernel_launch(void* const* d_in, const int* in_sizes, int n_in,
                              void* d_out, int out_size) {
    const float* ex = (const float*)d_in[0];
    (void)in_sizes; (void)n_in; (void)out_size;

    cudaFuncSetAttribute(k_gemm, cudaFuncAttributeMaxDynamicSharedMemorySize, DYN_SMEM);

    k_norm<<<Nn / 8, 256>>>(ex);

    k_gemm<<<NCTA_G, 256, DYN_SMEM>>>();

    k_red<<<RED_BLOCKS, 256>>>((float*)d_out);
}